// round 16
// baseline (speedup 1.0000x reference)
#include <cuda_runtime.h>

// REINFORCE fused kernel, GB300 sm_103a — R15
//
// out[0:T)      = generator_objective
// out[T:T+B*T)  = cumulative_rewards (row-major [B,T])
//
// ONE persistent kernel, grid=296 (148 SMs x 2 co-resident blocks,
// guaranteed by __launch_bounds__(512,2) + 104KB smem/block), software grid
// barriers, and the key change vs R14:
//
//   diff = cum - base is CACHED IN SHARED MEMORY across the barrier
//   (13 rows x 2048 cols x fp32 = 104KB; 14th row, when present, in regs).
//   Stage 3 therefore reads ONLY logp from gmem: total LTS traffic drops
//   235MB -> 168MB.
//
//   stage 1: suffix scan -> cum (gmem) + diff (smem/regs) + partial colsums.
//   [grid barrier]
//   stage 2: one warp per column sums 296 partials -> g_mean.
//   [grid barrier]
//   stage 3: adv = clip(diff - mean); obj += adv * logp (REDG atomics).

namespace {
constexpr int   Bn     = 4096;
constexpr int   Tn     = 2048;
constexpr float GAMMA  = 0.99f;
constexpr float CLIPV  = 5.0f;
constexpr int   TPB    = 512;    // thread k owns cols [4k, 4k+4)
constexpr int   NBLK   = 296;    // 148 SMs x 2 resident blocks
constexpr int   NWARP  = TPB / 32;      // 16
constexpr int   SROWS  = 13;     // diff rows held in smem (14th in regs)
constexpr int   SMEMB  = SROWS * Tn * 4;  // 106496 bytes dynamic smem
}

__device__ float    g_partA[NBLK][Tn];  // per-block partial colsum(diff)
__device__ float    g_mean[Tn];         // batch mean of diff
__device__ unsigned g_bar  = 0;         // grid-barrier arrival counter
__device__ unsigned g_done = 0;         // exit counter (for counter reset)

__device__ __forceinline__ float log_sigmoid(float x) {
    float t = __expf(-fabsf(x));
    return fminf(x, 0.f) - __logf(1.f + t);
}

// Software grid barrier. Safe only because all NBLK blocks are co-resident.
__device__ __forceinline__ void grid_barrier(unsigned target) {
    __threadfence();
    __syncthreads();
    if (threadIdx.x == 0) {
        atomicAdd(&g_bar, 1u);
        while (*(volatile unsigned*)&g_bar < target)
            __nanosleep(64);
    }
    __syncthreads();
    __threadfence();
}

__global__ __launch_bounds__(TPB, 2) void fused_kernel(
    const float* __restrict__ logits,
    const float* __restrict__ weight,
    const float* __restrict__ base,
    const float* __restrict__ logp,
    float* __restrict__ cumout,
    float* __restrict__ obj)
{
    extern __shared__ float sdiff[];     // [SROWS][Tn]
    __shared__ float Wsh[2][NWARP];

    const int tid  = threadIdx.x;
    const int lane = tid & 31;
    const int warp = tid >> 5;
    const int col0 = tid * 4;

    // variable row range: uniform SM fill with grid=296 (13 or 14 rows)
    const int r0 = (int)(((long)blockIdx.x       * Bn) / NBLK);
    const int r1 = (int)(((long)(blockIdx.x + 1) * Bn) / NBLK);
    const int nr = r1 - r0;              // 13 or 14

    // block 0 zeroes the objective accumulator (pre-barrier => ordered
    // before any stage-3 atomics)
    if (blockIdx.x == 0)
        *(float4*)(obj + col0) = make_float4(0.f, 0.f, 0.f, 0.f);

    // diff for the 14th row (when nr==14) lives in these registers
    float rg0 = 0.f, rg1 = 0.f, rg2 = 0.f, rg3 = 0.f;

    // ---------------- stage 1: discounted suffix scan ----------------
    {
        const float g1 = GAMMA;
        const float g2 = g1 * g1;
        const float g3 = g2 * g1;
        const float g4 = g2 * g2;          // chunk ratio
        const float w1  = g4;
        const float w2  = w1 * w1;         // gamma^8
        const float w4  = w2 * w2;         // gamma^16
        const float w8  = w4 * w4;         // gamma^32
        const float w16 = w8 * w8;         // gamma^64
        const float r128 = w16 * w16;      // warp ratio gamma^128

        // (gamma^4)^(31-lane) via one MUFU: log2(0.99^4) = -0.057998278
        const float r4p31 = exp2f((float)(31 - lane) * -0.05799828f);

        float d0 = 0.f, d1 = 0.f, d2 = 0.f, d3 = 0.f;

        unsigned off = (unsigned)r0 * Tn + col0;

        // prefetch l/w for first row (base off the critical path)
        float4 lv = __ldcs((const float4*)(logits + off));
        float4 wv = __ldcs((const float4*)(weight + off));

        #pragma unroll 2
        for (int li = 0; li < nr; ++li, off += Tn) {
            const float4 b = *(const float4*)(base + off);

            const float4 l = lv, w = wv;
            if (li + 1 < nr) {
                lv = __ldcs((const float4*)(logits + off + Tn));
                wv = __ldcs((const float4*)(weight + off + Tn));
            }

            // weighted rewards + local reverse suffix (chunk of 4)
            const float ls3 = w.w * log_sigmoid(l.w);
            const float ls2 = w.z * log_sigmoid(l.z) + g1 * ls3;
            const float ls1 = w.y * log_sigmoid(l.y) + g1 * ls2;
            const float ls0 = w.x * log_sigmoid(l.x) + g1 * ls1;

            // warp inclusive suffix scan over chunk heads, ratio gamma^4
            float v = ls0;
            float o;
            o = __shfl_down_sync(0xffffffffu, v, 1);  if (lane < 31) v += w1  * o;
            o = __shfl_down_sync(0xffffffffu, v, 2);  if (lane < 30) v += w2  * o;
            o = __shfl_down_sync(0xffffffffu, v, 4);  if (lane < 28) v += w4  * o;
            o = __shfl_down_sync(0xffffffffu, v, 8);  if (lane < 24) v += w8  * o;
            o = __shfl_down_sync(0xffffffffu, v, 16); if (lane < 16) v += w16 * o;
            float vn = __shfl_down_sync(0xffffffffu, v, 1);
            if (lane == 31) vn = 0.f;

            const int par = li & 1;
            if (lane == 0) Wsh[par][warp] = v;
            __syncthreads();                 // 1 barrier/row; parity = WAR safe

            // inclusive suffix over later warps, ratio gamma^128
            float swn = 0.f;
            #pragma unroll
            for (int u = NWARP - 1; u >= 1; --u)
                if (u > warp) swn = Wsh[par][u] + r128 * swn;

            // carry = full cum at col0+4
            const float C = vn + r4p31 * swn;

            const float c0 = ls0 + g4 * C;
            const float c1 = ls1 + g3 * C;
            const float c2 = ls2 + g2 * C;
            const float c3 = ls3 + g1 * C;

            *(float4*)(cumout + off) = make_float4(c0, c1, c2, c3);

            const float f0 = c0 - b.x;
            const float f1 = c1 - b.y;
            const float f2 = c2 - b.z;
            const float f3 = c3 - b.w;

            if (li < SROWS)
                *(float4*)(sdiff + li * Tn + col0) = make_float4(f0, f1, f2, f3);
            else { rg0 = f0; rg1 = f1; rg2 = f2; rg3 = f3; }

            d0 += f0; d1 += f1; d2 += f2; d3 += f3;
        }

        *(float4*)(&g_partA[blockIdx.x][col0]) = make_float4(d0, d1, d2, d3);
    }

    grid_barrier(NBLK);

    // ---------------- stage 2: column means ----------------
    {
        const int gw = blockIdx.x * NWARP + warp;   // 0 .. 4735
        if (gw < Tn) {
            float s = 0.f;
            for (int p = lane; p < NBLK; p += 32)   // L2-hot, high MLP
                s += g_partA[p][gw];
            s += __shfl_down_sync(0xffffffffu, s, 16);
            s += __shfl_down_sync(0xffffffffu, s, 8);
            s += __shfl_down_sync(0xffffffffu, s, 4);
            s += __shfl_down_sync(0xffffffffu, s, 2);
            s += __shfl_down_sync(0xffffffffu, s, 1);
            if (lane == 0) g_mean[gw] = s * (1.f / Bn);
        }
    }

    grid_barrier(2u * NBLK);

    // ---------------- stage 3: objective (logp is the ONLY gmem read) ------
    {
        const float4 m = *(const float4*)(g_mean + col0);

        float o0 = 0.f, o1 = 0.f, o2 = 0.f, o3 = 0.f;

        unsigned off = (unsigned)r0 * Tn + col0;
        int li = 0;

        // chunks of 4 rows: 4 gmem float4 loads + 4 LDS.128 in flight
        for (; li + 4 <= SROWS; li += 4, off += 4 * Tn) {
            const float4 p0 = __ldcs((const float4*)(logp + off));
            const float4 p1 = __ldcs((const float4*)(logp + off + Tn));
            const float4 p2 = __ldcs((const float4*)(logp + off + 2 * Tn));
            const float4 p3 = __ldcs((const float4*)(logp + off + 3 * Tn));
            const float4 f0 = *(const float4*)(sdiff + (li + 0) * Tn + col0);
            const float4 f1 = *(const float4*)(sdiff + (li + 1) * Tn + col0);
            const float4 f2 = *(const float4*)(sdiff + (li + 2) * Tn + col0);
            const float4 f3 = *(const float4*)(sdiff + (li + 3) * Tn + col0);

            #pragma unroll
            for (int k = 0; k < 4; ++k) {
                const float4 f = (k == 0) ? f0 : (k == 1) ? f1 : (k == 2) ? f2 : f3;
                const float4 p = (k == 0) ? p0 : (k == 1) ? p1 : (k == 2) ? p2 : p3;
                const float a0 = fminf(fmaxf(f.x - m.x, -CLIPV), CLIPV);
                const float a1 = fminf(fmaxf(f.y - m.y, -CLIPV), CLIPV);
                const float a2 = fminf(fmaxf(f.z - m.z, -CLIPV), CLIPV);
                const float a3 = fminf(fmaxf(f.w - m.w, -CLIPV), CLIPV);
                o0 += a0 * p.x;
                o1 += a1 * p.y;
                o2 += a2 * p.z;
                o3 += a3 * p.w;
            }
        }

        // remaining smem row (SROWS=13 -> one leftover: li=12)
        for (; li < SROWS; ++li, off += Tn) {
            const float4 p = __ldcs((const float4*)(logp + off));
            const float4 f = *(const float4*)(sdiff + li * Tn + col0);
            const float a0 = fminf(fmaxf(f.x - m.x, -CLIPV), CLIPV);
            const float a1 = fminf(fmaxf(f.y - m.y, -CLIPV), CLIPV);
            const float a2 = fminf(fmaxf(f.z - m.z, -CLIPV), CLIPV);
            const float a3 = fminf(fmaxf(f.w - m.w, -CLIPV), CLIPV);
            o0 += a0 * p.x;
            o1 += a1 * p.y;
            o2 += a2 * p.z;
            o3 += a3 * p.w;
        }

        // 14th row, if this block has one (diff kept in registers)
        if (nr > SROWS) {
            const float4 p = __ldcs((const float4*)(logp + off));
            const float a0 = fminf(fmaxf(rg0 - m.x, -CLIPV), CLIPV);
            const float a1 = fminf(fmaxf(rg1 - m.y, -CLIPV), CLIPV);
            const float a2 = fminf(fmaxf(rg2 - m.z, -CLIPV), CLIPV);
            const float a3 = fminf(fmaxf(rg3 - m.w, -CLIPV), CLIPV);
            o0 += a0 * p.x;
            o1 += a1 * p.y;
            o2 += a2 * p.z;
            o3 += a3 * p.w;
        }

        atomicAdd(&obj[col0 + 0], o0);
        atomicAdd(&obj[col0 + 1], o1);
        atomicAdd(&obj[col0 + 2], o2);
        atomicAdd(&obj[col0 + 3], o3);
    }

    // -------- counter reset by the last-finishing block (replay-safe) -------
    __syncthreads();
    if (tid == 0) {
        const unsigned d = atomicAdd(&g_done, 1u);
        if (d == NBLK - 1u) {
            g_bar  = 0u;
            g_done = 0u;
            __threadfence();
        }
    }
}

extern "C" void kernel_launch(void* const* d_in, const int* in_sizes, int n_in,
                              void* d_out, int out_size) {
    const float* logp   = (const float*)d_in[0];  // log_probs  [B,T]
    const float* logits = (const float*)d_in[1];  // logits     [B,T,1]
    const float* weight = (const float*)d_in[2];  // weight     [B,T]
    const float* base   = (const float*)d_in[3];  // baselines  [B,T,1]
    float* out = (float*)d_out;

    // opt in to >48KB dynamic smem (idempotent; executes outside capture)
    cudaFuncSetAttribute(fused_kernel,
                         cudaFuncAttributeMaxDynamicSharedMemorySize, SMEMB);

    fused_kernel<<<NBLK, TPB, SMEMB>>>(logits, weight, base, logp,
                                       out + Tn, out);
}

// round 17
// speedup vs baseline: 1.1753x; 1.1753x over previous
#include <cuda_runtime.h>

// REINFORCE fused kernel, GB300 sm_103a — R16
//
// out[0:T)      = generator_objective
// out[T:T+B*T)  = cumulative_rewards (row-major [B,T])
//
// 3 kernels — graft of the two best measured configurations:
//   phaseA      : R13 version (grid=296 = 148 SMs x occ2 uniform fill,
//                 13-14 rows/block, measured 24.5us).
//   reduce_mean : 4-accumulator MLP loop over the 296 L2-hot partials.
//   phaseB      : R9 version VERBATIM (grid=256, fixed ROWS_B=16, unroll 4,
//                 prefetch-1, cum/base default-cached -> L2 hits on phaseA's
//                 writes, logp evict-first; REDG atomics into out[0:T)).
//                 This config produced the best-ever 15.9us remainder.

namespace {
constexpr int   Bn     = 4096;
constexpr int   Tn     = 2048;
constexpr float GAMMA  = 0.99f;
constexpr float CLIPV  = 5.0f;
constexpr int   TPB    = 512;    // thread k owns cols [4k, 4k+4)
constexpr int   NBLK   = 296;    // phaseA: 148 SMs x 2 resident blocks
constexpr int   ROWS_B = 16;     // phaseB rows per block (fixed trip count)
constexpr int   NPB    = Bn / ROWS_B;   // 256 phaseB blocks
constexpr int   NWARP  = TPB / 32;      // 16
}

__device__ float g_partA[NBLK][Tn];  // per-block partial colsum(cum - base)
__device__ float g_mean[Tn];         // batch mean of (cum - base)

__device__ __forceinline__ float log_sigmoid(float x) {
    float t = __expf(-fabsf(x));
    return fminf(x, 0.f) - __logf(1.f + t);
}

__global__ __launch_bounds__(TPB, 2) void phaseA_kernel(
    const float* __restrict__ logits,
    const float* __restrict__ weight,
    const float* __restrict__ base,
    float* __restrict__ cumout,
    float* __restrict__ obj)
{
    __shared__ float Wsh[2][NWARP];

    const int tid  = threadIdx.x;
    const int lane = tid & 31;
    const int warp = tid >> 5;
    const int col0 = tid * 4;

    // variable row range: uniform SM fill with grid=296
    const int r0 = (int)(((long)blockIdx.x       * Bn) / NBLK);
    const int r1 = (int)(((long)(blockIdx.x + 1) * Bn) / NBLK);

    // block 0 zeroes the objective accumulator for phaseB's atomics
    if (blockIdx.x == 0)
        *(float4*)(obj + col0) = make_float4(0.f, 0.f, 0.f, 0.f);

    // gamma powers
    const float g1 = GAMMA;
    const float g2 = g1 * g1;
    const float g3 = g2 * g1;
    const float g4 = g2 * g2;          // chunk ratio
    const float w1  = g4;
    const float w2  = w1 * w1;         // gamma^8
    const float w4  = w2 * w2;         // gamma^16
    const float w8  = w4 * w4;         // gamma^32
    const float w16 = w8 * w8;         // gamma^64
    const float r128 = w16 * w16;      // warp ratio gamma^128

    // (gamma^4)^(31-lane) via one MUFU: log2(0.99^4) = -0.057998278
    const float r4p31 = exp2f((float)(31 - lane) * -0.05799828f);

    float d0 = 0.f, d1 = 0.f, d2 = 0.f, d3 = 0.f;

    unsigned off = (unsigned)r0 * Tn + col0;   // max 8.4M < 2^31

    // prefetch l/w for first row (base handled per-iteration, off critical path)
    float4 lv = __ldcs((const float4*)(logits + off));
    float4 wv = __ldcs((const float4*)(weight + off));

    #pragma unroll 2
    for (int r = r0; r < r1; ++r, off += Tn) {
        // issue base load early; consumed only by trailing dacc FMAs
        const float4 b = *(const float4*)(base + off);

        const float4 l = lv, w = wv;
        if (r + 1 < r1) {
            lv = __ldcs((const float4*)(logits + off + Tn));
            wv = __ldcs((const float4*)(weight + off + Tn));
        }

        // weighted rewards + local reverse suffix (chunk of 4)
        const float ls3 = w.w * log_sigmoid(l.w);
        const float ls2 = w.z * log_sigmoid(l.z) + g1 * ls3;
        const float ls1 = w.y * log_sigmoid(l.y) + g1 * ls2;
        const float ls0 = w.x * log_sigmoid(l.x) + g1 * ls1;

        // warp inclusive suffix scan over chunk heads, ratio gamma^4
        float v = ls0;
        float o;
        o = __shfl_down_sync(0xffffffffu, v, 1);  if (lane < 31) v += w1  * o;
        o = __shfl_down_sync(0xffffffffu, v, 2);  if (lane < 30) v += w2  * o;
        o = __shfl_down_sync(0xffffffffu, v, 4);  if (lane < 28) v += w4  * o;
        o = __shfl_down_sync(0xffffffffu, v, 8);  if (lane < 24) v += w8  * o;
        o = __shfl_down_sync(0xffffffffu, v, 16); if (lane < 16) v += w16 * o;
        float vn = __shfl_down_sync(0xffffffffu, v, 1);
        if (lane == 31) vn = 0.f;

        const int par = r & 1;
        if (lane == 0) Wsh[par][warp] = v;   // warp-span cum at warp start
        __syncthreads();                     // 1 barrier/row; parity = WAR safe

        // inclusive suffix over later warps, ratio gamma^128
        float swn = 0.f;
        #pragma unroll
        for (int u = NWARP - 1; u >= 1; --u)
            if (u > warp) swn = Wsh[par][u] + r128 * swn;

        // carry = full cum at col0+4
        const float C = vn + r4p31 * swn;

        const float c0 = ls0 + g4 * C;
        const float c1 = ls1 + g3 * C;
        const float c2 = ls2 + g2 * C;
        const float c3 = ls3 + g1 * C;

        *(float4*)(cumout + off) = make_float4(c0, c1, c2, c3);

        d0 += c0 - b.x;
        d1 += c1 - b.y;
        d2 += c2 - b.z;
        d3 += c3 - b.w;
    }

    *(float4*)(&g_partA[blockIdx.x][col0]) = make_float4(d0, d1, d2, d3);
}

// 64 blocks x 512 threads. Block owns 32 columns; warp w sums partials
// p = w, w+16, ... (coalesced 128B rows). 4 independent accumulators with
// batched loads (MLP=4); cross-warp combine in padded smem.
__global__ __launch_bounds__(512) void reduce_mean_kernel() {
    __shared__ float sh[16][33];
    const int lane = threadIdx.x & 31;
    const int w    = threadIdx.x >> 5;
    const int col  = blockIdx.x * 32 + lane;

    float s0 = 0.f, s1 = 0.f, s2 = 0.f, s3 = 0.f;
    int p = w;
    for (; p + 48 < NBLK; p += 64) {
        const float a = g_partA[p     ][col];
        const float b = g_partA[p + 16][col];
        const float c = g_partA[p + 32][col];
        const float d = g_partA[p + 48][col];
        s0 += a; s1 += b; s2 += c; s3 += d;
    }
    for (; p < NBLK; p += 16) s0 += g_partA[p][col];

    sh[w][lane] = (s0 + s1) + (s2 + s3);
    __syncthreads();

    if (w == 0) {
        float t = 0.f;
        #pragma unroll
        for (int u = 0; u < 16; ++u) t += sh[u][lane];
        g_mean[col] = t * (1.f / Bn);
    }
}

// R9 phaseB, verbatim: grid=256, fixed ROWS_B=16, unroll 4, prefetch-1.
__global__ __launch_bounds__(TPB) void phaseB_kernel(
    const float* __restrict__ cum,
    const float* __restrict__ base,
    const float* __restrict__ logp,
    float* __restrict__ obj)
{
    const int tid  = threadIdx.x;
    const int col0 = tid * 4;
    const int row0 = blockIdx.x * ROWS_B;

    const float4 m = *(const float4*)(g_mean + col0);

    float o0 = 0.f, o1 = 0.f, o2 = 0.f, o3 = 0.f;

    long off = (long)row0 * Tn + col0;

    // prefetch row 0; cum/base default-cached (L2-resident from phaseA)
    float4 cv = *(const float4*)(cum + off);
    float4 bv = *(const float4*)(base + off);
    float4 pv = __ldcs((const float4*)(logp + off));

    #pragma unroll 4
    for (int r = 0; r < ROWS_B; ++r) {
        const float4 c = cv, b = bv, p = pv;
        if (r + 1 < ROWS_B) {
            off += Tn;
            cv = *(const float4*)(cum + off);
            bv = *(const float4*)(base + off);
            pv = __ldcs((const float4*)(logp + off));
        }

        float a0 = c.x - b.x - m.x;
        float a1 = c.y - b.y - m.y;
        float a2 = c.z - b.z - m.z;
        float a3 = c.w - b.w - m.w;
        a0 = fminf(fmaxf(a0, -CLIPV), CLIPV);
        a1 = fminf(fmaxf(a1, -CLIPV), CLIPV);
        a2 = fminf(fmaxf(a2, -CLIPV), CLIPV);
        a3 = fminf(fmaxf(a3, -CLIPV), CLIPV);

        o0 += a0 * p.x;
        o1 += a1 * p.y;
        o2 += a2 * p.z;
        o3 += a3 * p.w;
    }

    // direct column reduction into the output (REDG, no return value)
    atomicAdd(&obj[col0 + 0], o0);
    atomicAdd(&obj[col0 + 1], o1);
    atomicAdd(&obj[col0 + 2], o2);
    atomicAdd(&obj[col0 + 3], o3);
}

extern "C" void kernel_launch(void* const* d_in, const int* in_sizes, int n_in,
                              void* d_out, int out_size) {
    const float* logp   = (const float*)d_in[0];  // log_probs  [B,T]
    const float* logits = (const float*)d_in[1];  // logits     [B,T,1]
    const float* weight = (const float*)d_in[2];  // weight     [B,T]
    const float* base   = (const float*)d_in[3];  // baselines  [B,T,1]
    float* out = (float*)d_out;

    phaseA_kernel<<<NBLK, TPB>>>(logits, weight, base, out + Tn, out);
    reduce_mean_kernel<<<Tn / 32, 512>>>();
    phaseB_kernel<<<NPB, TPB>>>(out + Tn, base, logp, out);
}